// round 1
// baseline (speedup 1.0000x reference)
#include <cuda_runtime.h>
#include <math.h>

// Problem shape (fixed by the dataset): B=2, S=8, N=2048, D=3
#define NPTS   2048
#define TPB    256
#define QPT    2                    // query points per thread
#define QPB    (TPB * QPT)          // 512 queries per block
#define CHUNKS (NPTS / QPB)         // 4 chunks per (set, direction)
#define NSETS  16                   // B*S
#define NBLK   (NSETS * 2 * CHUNKS) // 128 blocks

// Deterministic two-stage reduction scratch (device globals: no allocation).
__device__ float g_loss_part[NBLK];        // sum of smooth_l1 over the block's queries
__device__ float g_cent_part[NBLK][3];     // sum of query coords (centroid partials)

__device__ __forceinline__ float smooth_l1(float a, float b) {
    float d = fabsf(a - b);
    return (d < 1.0f) ? (0.5f * d * d) : (d - 0.5f);
}

__global__ __launch_bounds__(TPB)
void chamfer_kernel(const float* __restrict__ Xv, const float* __restrict__ Tv) {
    const int blk   = blockIdx.x;
    const int set   = blk / (2 * CHUNKS);
    const int rem   = blk % (2 * CHUNKS);
    const int dir   = rem / CHUNKS;      // 0: queries=X_v, db=target ; 1: swapped
    const int chunk = rem % CHUNKS;

    const float* __restrict__ qg = (dir == 0 ? Xv : Tv) + set * NPTS * 3;
    const float* __restrict__ dg = (dir == 0 ? Tv : Xv) + set * NPTS * 3;

    __shared__ float4 db[NPTS];          // 32 KB: {x, y, z, ||t||^2}
    __shared__ float4 red4[TPB];         // 4 KB reduction buffer

    // Stage database points + squared norms into shared.
    for (int i = threadIdx.x; i < NPTS; i += TPB) {
        float x = dg[i * 3 + 0];
        float y = dg[i * 3 + 1];
        float z = dg[i * 3 + 2];
        float n = x * x;
        n = fmaf(y, y, n);
        n = fmaf(z, z, n);
        db[i] = make_float4(x, y, z, n);
    }
    __syncthreads();

    // Load this thread's QPT query points.
    float qx[QPT], qy[QPT], qz[QPT], p2[QPT];
    int   qi[QPT];
#pragma unroll
    for (int q = 0; q < QPT; q++) {
        qi[q] = chunk * QPB + q * TPB + threadIdx.x;   // coalesced-ish
        qx[q] = qg[qi[q] * 3 + 0];
        qy[q] = qg[qi[q] * 3 + 1];
        qz[q] = qg[qi[q] * 3 + 2];
        float n = qx[q] * qx[q];
        n = fmaf(qy[q], qy[q], n);
        n = fmaf(qz[q], qz[q], n);
        p2[q] = n;
    }

    float bd[QPT];
    int   bj[QPT];
#pragma unroll
    for (int q = 0; q < QPT; q++) { bd[q] = 3.4e38f; bj[q] = 0; }

    // Main pairwise loop: dist = (p2 + t2) - 2*cross, strict '<' keeps first index.
#pragma unroll 4
    for (int j = 0; j < NPTS; j++) {
        float4 t = db[j];
#pragma unroll
        for (int q = 0; q < QPT; q++) {
            float c = qx[q] * t.x;
            c = fmaf(qy[q], t.y, c);
            c = fmaf(qz[q], t.z, c);
            float d = fmaf(-2.0f, c, p2[q] + t.w);
            bool lt = d < bd[q];
            bd[q] = lt ? d : bd[q];
            bj[q] = lt ? j : bj[q];
        }
    }

    // Per-thread partial sums: smooth_l1 vs nearest neighbor, plus centroid sums.
    float sl = 0.0f, cx = 0.0f, cy = 0.0f, cz = 0.0f;
#pragma unroll
    for (int q = 0; q < QPT; q++) {
        float4 nb = db[bj[q]];
        sl += smooth_l1(qx[q], nb.x);
        sl += smooth_l1(qy[q], nb.y);
        sl += smooth_l1(qz[q], nb.z);
        cx += qx[q];
        cy += qy[q];
        cz += qz[q];
    }

    // Deterministic block reduction (fixed tree order).
    red4[threadIdx.x] = make_float4(sl, cx, cy, cz);
    __syncthreads();
    for (int s = TPB / 2; s > 0; s >>= 1) {
        if (threadIdx.x < s) {
            float4 a = red4[threadIdx.x];
            float4 b = red4[threadIdx.x + s];
            red4[threadIdx.x] = make_float4(a.x + b.x, a.y + b.y, a.z + b.z, a.w + b.w);
        }
        __syncthreads();
    }
    if (threadIdx.x == 0) {
        float4 r = red4[0];
        g_loss_part[blk]    = r.x;
        g_cent_part[blk][0] = r.y;
        g_cent_part[blk][1] = r.z;
        g_cent_part[blk][2] = r.w;
    }
}

__global__ void finalize_kernel(const float* __restrict__ w, float* __restrict__ out) {
    const int t = threadIdx.x;  // 32 threads, 1 warp
    float lp = 0.0f, lc = 0.0f;
    if (t < NSETS) {
        // per_set = (sum over both directions of smooth_l1 sums) / (N*D)
        float s = 0.0f;
        for (int d = 0; d < 2; d++)
            for (int c = 0; c < CHUNKS; c++)
                s += g_loss_part[(t * 2 + d) * CHUNKS + c];
        lp = s * (1.0f / (float)(NPTS * 3)) * w[t];

        // Centroid loss partials
        float pc0 = 0, pc1 = 0, pc2 = 0, tc0 = 0, tc1 = 0, tc2 = 0;
        for (int c = 0; c < CHUNKS; c++) {
            int b0 = (t * 2 + 0) * CHUNKS + c;   // dir 0 queries = X_v
            int b1 = (t * 2 + 1) * CHUNKS + c;   // dir 1 queries = target
            pc0 += g_cent_part[b0][0]; pc1 += g_cent_part[b0][1]; pc2 += g_cent_part[b0][2];
            tc0 += g_cent_part[b1][0]; tc1 += g_cent_part[b1][1]; tc2 += g_cent_part[b1][2];
        }
        const float inv_n = 1.0f / (float)NPTS;
        lc += smooth_l1(pc0 * inv_n, tc0 * inv_n);
        lc += smooth_l1(pc1 * inv_n, tc1 * inv_n);
        lc += smooth_l1(pc2 * inv_n, tc2 * inv_n);
    }
    // Fixed-order warp reduction (deterministic).
#pragma unroll
    for (int o = 16; o > 0; o >>= 1) {
        lp += __shfl_down_sync(0xffffffff, lp, o);
        lc += __shfl_down_sync(0xffffffff, lc, o);
    }
    if (t == 0) {
        out[0] = lp * 0.5f;          // / B  (B=2)
        out[1] = lc * (1.0f / 6.0f); // / (B*3)
    }
}

extern "C" void kernel_launch(void* const* d_in, const int* in_sizes, int n_in,
                              void* d_out, int out_size) {
    const float* Xv = (const float*)d_in[0];
    const float* Tv = (const float*)d_in[1];
    const float* w  = (const float*)d_in[2];
    float* out = (float*)d_out;

    chamfer_kernel<<<NBLK, TPB>>>(Xv, Tv);
    finalize_kernel<<<1, 32>>>(w, out);
}

// round 2
// speedup vs baseline: 1.0487x; 1.0487x over previous
#include <cuda_runtime.h>
#include <math.h>

typedef unsigned long long u64;

// Problem shape (fixed): B=2, S=8, N=2048, D=3
#define NPTS   2048
#define TPB    256
#define QPT    2
#define QPB    (TPB * QPT)          // 512 queries per block
#define CHUNKS (NPTS / QPB)         // 4
#define NSETS  16                   // B*S
#define NBLK   (NSETS * 2 * CHUNKS) // 128 blocks

__device__ float g_loss_part[NBLK];
__device__ float g_cent_part[NBLK][3];
__device__ unsigned int g_ctr = 0;   // self-resetting completion counter

__device__ __forceinline__ float smooth_l1(float a, float b) {
    float d = fabsf(a - b);
    return (d < 1.0f) ? (0.5f * d * d) : (d - 0.5f);
}

// Blackwell packed f32x2 FMA (only reachable via PTX)
#define FMA2(d, a, b, c) \
    asm("fma.rn.f32x2 %0, %1, %2, %3;" : "=l"(d) : "l"(a), "l"(b), "l"(c))
#define PACK2(d, lo, hi) \
    asm("mov.b64 %0, {%1, %2};" : "=l"(d) : "f"(lo), "f"(hi))
#define UNPACK2(lo, hi, s) \
    asm("mov.b64 {%0, %1}, %2;" : "=f"(lo), "=f"(hi) : "l"(s))

__global__ __launch_bounds__(TPB)
void chamfer_kernel(const float* __restrict__ Xv, const float* __restrict__ Tv,
                    const float* __restrict__ w, float* __restrict__ out)
{
    const int tid   = threadIdx.x;
    const int blk   = blockIdx.x;
    const int set   = blk / (2 * CHUNKS);
    const int rem   = blk % (2 * CHUNKS);
    const int dir   = rem / CHUNKS;      // 0: queries=X_v, db=target ; 1: swapped
    const int chunk = rem % CHUNKS;

    const float* __restrict__ qg = (dir == 0 ? Xv : Tv) + set * NPTS * 3;
    const float* __restrict__ dg = (dir == 0 ? Tv : Xv) + set * NPTS * 3;

    // Database tile, pre-interleaved for f32x2 over consecutive-j pairs.
    // shA[jp] = { (-2x_j, -2x_{j+1}) , (-2y_j, -2y_{j+1}) }
    // shB[jp] = { (-2z_j, -2z_{j+1}) , ( t2_j,  t2_{j+1}) }
    __shared__ ulonglong2 shA[NPTS / 2];   // 16 KB
    __shared__ ulonglong2 shB[NPTS / 2];   // 16 KB
    __shared__ float4 red4[TPB];           // 4 KB
    __shared__ unsigned int is_last;

    {
        float* fA = (float*)shA;
        float* fB = (float*)shB;
        for (int i = tid; i < NPTS; i += TPB) {
            float x = dg[i * 3 + 0];
            float y = dg[i * 3 + 1];
            float z = dg[i * 3 + 2];
            float n = x * x;
            n = fmaf(y, y, n);
            n = fmaf(z, z, n);
            int jp = i >> 1, l = i & 1;
            fA[4 * jp + 0 + l] = -2.0f * x;
            fA[4 * jp + 2 + l] = -2.0f * y;
            fB[4 * jp + 0 + l] = -2.0f * z;
            fB[4 * jp + 2 + l] = n;
        }
    }
    __syncthreads();

    // Query points for this thread (scalar + lane-duplicated packed forms).
    float qx[QPT], qy[QPT], qz[QPT];
    u64   qx2[QPT], qy2[QPT], qz2[QPT];
#pragma unroll
    for (int q = 0; q < QPT; q++) {
        int qi = chunk * QPB + q * TPB + tid;
        qx[q] = qg[qi * 3 + 0];
        qy[q] = qg[qi * 3 + 1];
        qz[q] = qg[qi * 3 + 2];
        PACK2(qx2[q], qx[q], qx[q]);
        PACK2(qy2[q], qy[q], qy[q]);
        PACK2(qz2[q], qz[q], qz[q]);
    }

    float bd[QPT];
    int   bj[QPT];
#pragma unroll
    for (int q = 0; q < QPT; q++) { bd[q] = 3.4e38f; bj[q] = 0; }

    // Argmin key: t2_j - 2*q.t_j   (p2 is constant per query -> dropped).
    // Strict '<' keeps first index on exact ties, matching jnp.argmin.
#pragma unroll 4
    for (int jp = 0; jp < NPTS / 2; jp++) {
        ulonglong2 va = shA[jp];   // {mx2, my2}
        ulonglong2 vb = shB[jp];   // {mz2, t2x2}
#pragma unroll
        for (int q = 0; q < QPT; q++) {
            u64 acc = vb.y;
            FMA2(acc, qx2[q], va.x, acc);
            FMA2(acc, qy2[q], va.y, acc);
            FMA2(acc, qz2[q], vb.x, acc);
            float d0, d1;
            UNPACK2(d0, d1, acc);
            if (d0 < bd[q]) { bd[q] = d0; bj[q] = 2 * jp; }
            if (d1 < bd[q]) { bd[q] = d1; bj[q] = 2 * jp + 1; }
        }
    }

    // Recover nearest-neighbor coords from the -2x packed tile; partial sums.
    float sl = 0.0f, cx = 0.0f, cy = 0.0f, cz = 0.0f;
#pragma unroll
    for (int q = 0; q < QPT; q++) {
        int j = bj[q], jp = j >> 1, l = j & 1;
        const float* fA = (const float*)&shA[jp];
        const float* fB = (const float*)&shB[jp];
        float nx = -0.5f * fA[0 + l];
        float ny = -0.5f * fA[2 + l];
        float nz = -0.5f * fB[0 + l];
        sl += smooth_l1(qx[q], nx);
        sl += smooth_l1(qy[q], ny);
        sl += smooth_l1(qz[q], nz);
        cx += qx[q];
        cy += qy[q];
        cz += qz[q];
    }

    // Deterministic block reduction (fixed tree order).
    red4[tid] = make_float4(sl, cx, cy, cz);
    __syncthreads();
    for (int s = TPB / 2; s > 0; s >>= 1) {
        if (tid < s) {
            float4 a = red4[tid];
            float4 b = red4[tid + s];
            red4[tid] = make_float4(a.x + b.x, a.y + b.y, a.z + b.z, a.w + b.w);
        }
        __syncthreads();
    }
    if (tid == 0) {
        float4 r = red4[0];
        g_loss_part[blk]    = r.x;
        g_cent_part[blk][0] = r.y;
        g_cent_part[blk][1] = r.z;
        g_cent_part[blk][2] = r.w;
        __threadfence();
        unsigned int v = atomicAdd(&g_ctr, 1u);
        is_last = (v == NBLK - 1) ? 1u : 0u;
    }
    __syncthreads();

    // Last block finalizes (deterministic; counter self-resets for graph replay).
    if (is_last && tid < 32) {
        __threadfence();
        const int t = tid;
        float lp = 0.0f, lc = 0.0f;
        if (t < NSETS) {
            float s = 0.0f;
            for (int d = 0; d < 2; d++)
                for (int c = 0; c < CHUNKS; c++)
                    s += g_loss_part[(t * 2 + d) * CHUNKS + c];
            lp = s * (1.0f / (float)(NPTS * 3)) * w[t];

            float pc0 = 0, pc1 = 0, pc2 = 0, tc0 = 0, tc1 = 0, tc2 = 0;
            for (int c = 0; c < CHUNKS; c++) {
                int b0 = (t * 2 + 0) * CHUNKS + c;   // dir 0 queries = X_v
                int b1 = (t * 2 + 1) * CHUNKS + c;   // dir 1 queries = target
                pc0 += g_cent_part[b0][0]; pc1 += g_cent_part[b0][1]; pc2 += g_cent_part[b0][2];
                tc0 += g_cent_part[b1][0]; tc1 += g_cent_part[b1][1]; tc2 += g_cent_part[b1][2];
            }
            const float inv_n = 1.0f / (float)NPTS;
            lc += smooth_l1(pc0 * inv_n, tc0 * inv_n);
            lc += smooth_l1(pc1 * inv_n, tc1 * inv_n);
            lc += smooth_l1(pc2 * inv_n, tc2 * inv_n);
        }
#pragma unroll
        for (int o = 16; o > 0; o >>= 1) {
            lp += __shfl_down_sync(0xffffffff, lp, o);
            lc += __shfl_down_sync(0xffffffff, lc, o);
        }
        if (t == 0) {
            out[0] = lp * 0.5f;          // / B
            out[1] = lc * (1.0f / 6.0f); // / (B*3)
            g_ctr = 0;                   // reset for next graph replay
        }
    }
}

extern "C" void kernel_launch(void* const* d_in, const int* in_sizes, int n_in,
                              void* d_out, int out_size) {
    const float* Xv = (const float*)d_in[0];
    const float* Tv = (const float*)d_in[1];
    const float* w  = (const float*)d_in[2];
    float* out = (float*)d_out;

    chamfer_kernel<<<NBLK, TPB>>>(Xv, Tv, w, out);
}

// round 3
// speedup vs baseline: 1.0825x; 1.0322x over previous
#include <cuda_runtime.h>
#include <math.h>

typedef unsigned long long u64;

// Problem shape (fixed): B=2, S=8, N=2048, D=3
#define NPTS   2048
#define TPB    256
#define QPT    2
#define QPB    (TPB * QPT)          // 512 queries per block
#define CHUNKS (NPTS / QPB)         // 4
#define NSETS  16                   // B*S
#define NBLK   (NSETS * 2 * CHUNKS) // 128 blocks

#define IDX_MASK 0x7FFu             // 11 bits for j in [0, 2048)
#define KEY_MASK 0xFFFFF800u

__device__ float g_loss_part[NBLK];
__device__ float g_cent_part[NBLK][3];
__device__ unsigned int g_ctr = 0;   // self-resetting completion counter

__device__ __forceinline__ float smooth_l1(float a, float b) {
    float d = fabsf(a - b);
    return (d < 1.0f) ? (0.5f * d * d) : (d - 0.5f);
}

// Blackwell packed f32x2 FMA (only reachable via PTX)
#define FMA2(d, a, b, c) \
    asm("fma.rn.f32x2 %0, %1, %2, %3;" : "=l"(d) : "l"(a), "l"(b), "l"(c))
#define PACK2(d, lo, hi) \
    asm("mov.b64 %0, {%1, %2};" : "=l"(d) : "f"(lo), "f"(hi))
#define UNPACK2(lo, hi, s) \
    asm("mov.b64 {%0, %1}, %2;" : "=f"(lo), "=f"(hi) : "l"(s))

__global__ __launch_bounds__(TPB)
void chamfer_kernel(const float* __restrict__ Xv, const float* __restrict__ Tv,
                    const float* __restrict__ w, float* __restrict__ out)
{
    const int tid   = threadIdx.x;
    const int blk   = blockIdx.x;
    const int set   = blk / (2 * CHUNKS);
    const int rem   = blk % (2 * CHUNKS);
    const int dir   = rem / CHUNKS;      // 0: queries=X_v, db=target ; 1: swapped
    const int chunk = rem % CHUNKS;

    const float* __restrict__ qg = (dir == 0 ? Xv : Tv) + set * NPTS * 3;
    const float* __restrict__ dg = (dir == 0 ? Tv : Xv) + set * NPTS * 3;

    // Database tile, pre-interleaved for f32x2 over consecutive-j pairs.
    // shA[jp] = { (-2x_j, -2x_{j+1}) , (-2y_j, -2y_{j+1}) }
    // shB[jp] = { (-2z_j, -2z_{j+1}) , ( t2_j,  t2_{j+1}) }
    __shared__ ulonglong2 shA[NPTS / 2];   // 16 KB
    __shared__ ulonglong2 shB[NPTS / 2];   // 16 KB
    __shared__ float4 red4[TPB];           // 4 KB
    __shared__ unsigned int is_last;

    {
        float* fA = (float*)shA;
        float* fB = (float*)shB;
        for (int i = tid; i < NPTS; i += TPB) {
            float x = dg[i * 3 + 0];
            float y = dg[i * 3 + 1];
            float z = dg[i * 3 + 2];
            float n = x * x;
            n = fmaf(y, y, n);
            n = fmaf(z, z, n);
            int jp = i >> 1, l = i & 1;
            fA[4 * jp + 0 + l] = -2.0f * x;
            fA[4 * jp + 2 + l] = -2.0f * y;
            fB[4 * jp + 0 + l] = -2.0f * z;
            fB[4 * jp + 2 + l] = n;
        }
    }
    __syncthreads();

    // Query points (scalar + lane-duplicated packed forms).
    float qx[QPT], qy[QPT], qz[QPT];
    u64   qx2[QPT], qy2[QPT], qz2[QPT];
#pragma unroll
    for (int q = 0; q < QPT; q++) {
        int qi = chunk * QPB + q * TPB + tid;
        qx[q] = qg[qi * 3 + 0];
        qy[q] = qg[qi * 3 + 1];
        qz[q] = qg[qi * 3 + 2];
        PACK2(qx2[q], qx[q], qx[q]);
        PACK2(qy2[q], qy[q], qy[q]);
        PACK2(qz2[q], qz[q], qz[q]);
    }

    // Argmin via index-in-mantissa keys: key = (bits(d) & KEY_MASK) | j.
    // Two independent FMNMX chains per query (even/odd candidate lanes).
    float m0[QPT], m1[QPT];
#pragma unroll
    for (int q = 0; q < QPT; q++) { m0[q] = 3.0e38f; m1[q] = 3.0e38f; }

    // Argmin key: t2_j - 2*q.t_j   (p2 constant per query -> dropped).
#pragma unroll 4
    for (int jp = 0; jp < NPTS / 2; jp++) {
        ulonglong2 va = shA[jp];   // {mx2, my2}
        ulonglong2 vb = shB[jp];   // {mz2, t2x2}
        unsigned j0 = (unsigned)(2 * jp);
        unsigned j1 = j0 + 1;
#pragma unroll
        for (int q = 0; q < QPT; q++) {
            u64 acc = vb.y;
            FMA2(acc, qx2[q], va.x, acc);
            FMA2(acc, qy2[q], va.y, acc);
            FMA2(acc, qz2[q], vb.x, acc);
            float d0, d1;
            UNPACK2(d0, d1, acc);
            unsigned k0 = (__float_as_uint(d0) & KEY_MASK) | j0;  // one LOP3
            unsigned k1 = (__float_as_uint(d1) & KEY_MASK) | j1;  // one LOP3
            m0[q] = fminf(m0[q], __uint_as_float(k0));            // FMNMX, lat 4
            m1[q] = fminf(m1[q], __uint_as_float(k1));            // FMNMX, lat 4
        }
    }

    // Recover nearest neighbor from key low bits; per-thread partial sums.
    float sl = 0.0f, cx = 0.0f, cy = 0.0f, cz = 0.0f;
#pragma unroll
    for (int q = 0; q < QPT; q++) {
        float mk = fminf(m0[q], m1[q]);
        int j = (int)(__float_as_uint(mk) & IDX_MASK);
        int jp = j >> 1, l = j & 1;
        const float* fA = (const float*)&shA[jp];
        const float* fB = (const float*)&shB[jp];
        float nx = -0.5f * fA[0 + l];
        float ny = -0.5f * fA[2 + l];
        float nz = -0.5f * fB[0 + l];
        sl += smooth_l1(qx[q], nx);
        sl += smooth_l1(qy[q], ny);
        sl += smooth_l1(qz[q], nz);
        cx += qx[q];
        cy += qy[q];
        cz += qz[q];
    }

    // Deterministic block reduction (fixed tree order).
    red4[tid] = make_float4(sl, cx, cy, cz);
    __syncthreads();
    for (int s = TPB / 2; s > 0; s >>= 1) {
        if (tid < s) {
            float4 a = red4[tid];
            float4 b = red4[tid + s];
            red4[tid] = make_float4(a.x + b.x, a.y + b.y, a.z + b.z, a.w + b.w);
        }
        __syncthreads();
    }
    if (tid == 0) {
        float4 r = red4[0];
        g_loss_part[blk]    = r.x;
        g_cent_part[blk][0] = r.y;
        g_cent_part[blk][1] = r.z;
        g_cent_part[blk][2] = r.w;
        __threadfence();
        unsigned int v = atomicAdd(&g_ctr, 1u);
        is_last = (v == NBLK - 1) ? 1u : 0u;
    }
    __syncthreads();

    // Last block finalizes (deterministic; counter self-resets for graph replay).
    if (is_last && tid < 32) {
        __threadfence();
        const int t = tid;
        float lp = 0.0f, lc = 0.0f;
        if (t < NSETS) {
            float s = 0.0f;
            for (int d = 0; d < 2; d++)
                for (int c = 0; c < CHUNKS; c++)
                    s += g_loss_part[(t * 2 + d) * CHUNKS + c];
            lp = s * (1.0f / (float)(NPTS * 3)) * w[t];

            float pc0 = 0, pc1 = 0, pc2 = 0, tc0 = 0, tc1 = 0, tc2 = 0;
            for (int c = 0; c < CHUNKS; c++) {
                int b0 = (t * 2 + 0) * CHUNKS + c;   // dir 0 queries = X_v
                int b1 = (t * 2 + 1) * CHUNKS + c;   // dir 1 queries = target
                pc0 += g_cent_part[b0][0]; pc1 += g_cent_part[b0][1]; pc2 += g_cent_part[b0][2];
                tc0 += g_cent_part[b1][0]; tc1 += g_cent_part[b1][1]; tc2 += g_cent_part[b1][2];
            }
            const float inv_n = 1.0f / (float)NPTS;
            lc += smooth_l1(pc0 * inv_n, tc0 * inv_n);
            lc += smooth_l1(pc1 * inv_n, tc1 * inv_n);
            lc += smooth_l1(pc2 * inv_n, tc2 * inv_n);
        }
#pragma unroll
        for (int o = 16; o > 0; o >>= 1) {
            lp += __shfl_down_sync(0xffffffff, lp, o);
            lc += __shfl_down_sync(0xffffffff, lc, o);
        }
        if (t == 0) {
            out[0] = lp * 0.5f;          // / B
            out[1] = lc * (1.0f / 6.0f); // / (B*3)
            g_ctr = 0;                   // reset for next graph replay
        }
    }
}

extern "C" void kernel_launch(void* const* d_in, const int* in_sizes, int n_in,
                              void* d_out, int out_size) {
    const float* Xv = (const float*)d_in[0];
    const float* Tv = (const float*)d_in[1];
    const float* w  = (const float*)d_in[2];
    float* out = (float*)d_out;

    chamfer_kernel<<<NBLK, TPB>>>(Xv, Tv, w, out);
}

// round 4
// speedup vs baseline: 1.1298x; 1.0437x over previous
#include <cuda_runtime.h>
#include <math.h>

typedef unsigned long long u64;

// Problem shape (fixed): B=2, S=8, N=2048, D=3
#define NPTS   2048
#define TPB    128
#define QPB    TPB                  // 128 queries per block (1 per thread)
#define CHUNKS (NPTS / QPB)         // 16
#define NSETS  16                   // B*S
#define NBLK   (NSETS * 2 * CHUNKS) // 512 blocks

#define IDX_MASK 0x7FFu             // 11 bits for j in [0, 2048)
#define KEY_MASK 0xFFFFF800u

__device__ float g_loss_part[NBLK];
__device__ float g_cent_part[NBLK][3];
__device__ unsigned int g_ctr = 0;   // self-resetting completion counter

__device__ __forceinline__ float smooth_l1(float a, float b) {
    float d = fabsf(a - b);
    return (d < 1.0f) ? (0.5f * d * d) : (d - 0.5f);
}

// Blackwell packed f32x2 FMA (only reachable via PTX)
#define FMA2(d, a, b, c) \
    asm("fma.rn.f32x2 %0, %1, %2, %3;" : "=l"(d) : "l"(a), "l"(b), "l"(c))
#define PACK2(d, lo, hi) \
    asm("mov.b64 %0, {%1, %2};" : "=l"(d) : "f"(lo), "f"(hi))
#define UNPACK2(lo, hi, s) \
    asm("mov.b64 {%0, %1}, %2;" : "=f"(lo), "=f"(hi) : "l"(s))

__global__ __launch_bounds__(TPB)
void chamfer_kernel(const float* __restrict__ Xv, const float* __restrict__ Tv,
                    const float* __restrict__ w, float* __restrict__ out)
{
    const int tid   = threadIdx.x;
    const int blk   = blockIdx.x;
    const int set   = blk / (2 * CHUNKS);
    const int rem   = blk % (2 * CHUNKS);
    const int dir   = rem / CHUNKS;      // 0: queries=X_v, db=target ; 1: swapped
    const int chunk = rem % CHUNKS;

    const float* __restrict__ qg = (dir == 0 ? Xv : Tv) + set * NPTS * 3;
    const float* __restrict__ dg = (dir == 0 ? Tv : Xv) + set * NPTS * 3;

    // Database tile, pre-interleaved for f32x2 over consecutive-j pairs.
    // shA[jp] = { (-2x_j, -2x_{j+1}) , (-2y_j, -2y_{j+1}) }
    // shB[jp] = { (-2z_j, -2z_{j+1}) , ( t2_j,  t2_{j+1}) }
    __shared__ ulonglong2 shA[NPTS / 2];   // 16 KB
    __shared__ ulonglong2 shB[NPTS / 2];   // 16 KB
    __shared__ float4 red4[TPB];           // 2 KB
    __shared__ unsigned int is_last;

    {
        float* fA = (float*)shA;
        float* fB = (float*)shB;
        for (int i = tid; i < NPTS; i += TPB) {
            float x = dg[i * 3 + 0];
            float y = dg[i * 3 + 1];
            float z = dg[i * 3 + 2];
            float n = x * x;
            n = fmaf(y, y, n);
            n = fmaf(z, z, n);
            int jp = i >> 1, l = i & 1;
            fA[4 * jp + 0 + l] = -2.0f * x;
            fA[4 * jp + 2 + l] = -2.0f * y;
            fB[4 * jp + 0 + l] = -2.0f * z;
            fB[4 * jp + 2 + l] = n;
        }
    }
    __syncthreads();

    // This thread's single query point (scalar + lane-duplicated packed forms).
    const int qi = chunk * QPB + tid;
    const float qx = qg[qi * 3 + 0];
    const float qy = qg[qi * 3 + 1];
    const float qz = qg[qi * 3 + 2];
    u64 qx2, qy2, qz2;
    PACK2(qx2, qx, qx);
    PACK2(qy2, qy, qy);
    PACK2(qz2, qz, qz);

    // Argmin via index-in-mantissa keys: key = (bits(d) & KEY_MASK) | j.
    // Two independent lat-4 FMNMX chains (even/odd candidate lanes).
    float m0 = 3.0e38f, m1 = 3.0e38f;

    // Argmin key: t2_j - 2*q.t_j   (p2 constant per query -> dropped).
#pragma unroll 8
    for (int jp = 0; jp < NPTS / 2; jp++) {
        ulonglong2 va = shA[jp];   // {mx2, my2}
        ulonglong2 vb = shB[jp];   // {mz2, t2x2}
        unsigned j0 = (unsigned)(2 * jp);
        u64 acc = vb.y;
        FMA2(acc, qx2, va.x, acc);
        FMA2(acc, qy2, va.y, acc);
        FMA2(acc, qz2, vb.x, acc);
        float d0, d1;
        UNPACK2(d0, d1, acc);
        unsigned k0 = (__float_as_uint(d0) & KEY_MASK) | j0;        // one LOP3
        unsigned k1 = (__float_as_uint(d1) & KEY_MASK) | (j0 + 1);  // one LOP3
        m0 = fminf(m0, __uint_as_float(k0));                        // FMNMX
        m1 = fminf(m1, __uint_as_float(k1));                        // FMNMX
    }

    // Recover nearest neighbor from key low bits; per-thread partials.
    float sl, cx, cy, cz;
    {
        float mk = fminf(m0, m1);
        int j = (int)(__float_as_uint(mk) & IDX_MASK);
        int jp = j >> 1, l = j & 1;
        const float* fA = (const float*)&shA[jp];
        const float* fB = (const float*)&shB[jp];
        float nx = -0.5f * fA[0 + l];
        float ny = -0.5f * fA[2 + l];
        float nz = -0.5f * fB[0 + l];
        sl  = smooth_l1(qx, nx);
        sl += smooth_l1(qy, ny);
        sl += smooth_l1(qz, nz);
        cx = qx; cy = qy; cz = qz;
    }

    // Deterministic block reduction (fixed tree order).
    red4[tid] = make_float4(sl, cx, cy, cz);
    __syncthreads();
    for (int s = TPB / 2; s > 0; s >>= 1) {
        if (tid < s) {
            float4 a = red4[tid];
            float4 b = red4[tid + s];
            red4[tid] = make_float4(a.x + b.x, a.y + b.y, a.z + b.z, a.w + b.w);
        }
        __syncthreads();
    }
    if (tid == 0) {
        float4 r = red4[0];
        g_loss_part[blk]    = r.x;
        g_cent_part[blk][0] = r.y;
        g_cent_part[blk][1] = r.z;
        g_cent_part[blk][2] = r.w;
        __threadfence();
        unsigned int v = atomicAdd(&g_ctr, 1u);
        is_last = (v == NBLK - 1) ? 1u : 0u;
    }
    __syncthreads();

    // Last block finalizes (deterministic; counter self-resets for graph replay).
    if (is_last && tid < 32) {
        __threadfence();
        const int t = tid;
        float lp = 0.0f, lc = 0.0f;
        if (t < NSETS) {
            float s = 0.0f;
            for (int d = 0; d < 2; d++)
                for (int c = 0; c < CHUNKS; c++)
                    s += g_loss_part[(t * 2 + d) * CHUNKS + c];
            lp = s * (1.0f / (float)(NPTS * 3)) * w[t];

            float pc0 = 0, pc1 = 0, pc2 = 0, tc0 = 0, tc1 = 0, tc2 = 0;
            for (int c = 0; c < CHUNKS; c++) {
                int b0 = (t * 2 + 0) * CHUNKS + c;   // dir 0 queries = X_v
                int b1 = (t * 2 + 1) * CHUNKS + c;   // dir 1 queries = target
                pc0 += g_cent_part[b0][0]; pc1 += g_cent_part[b0][1]; pc2 += g_cent_part[b0][2];
                tc0 += g_cent_part[b1][0]; tc1 += g_cent_part[b1][1]; tc2 += g_cent_part[b1][2];
            }
            const float inv_n = 1.0f / (float)NPTS;
            lc += smooth_l1(pc0 * inv_n, tc0 * inv_n);
            lc += smooth_l1(pc1 * inv_n, tc1 * inv_n);
            lc += smooth_l1(pc2 * inv_n, tc2 * inv_n);
        }
#pragma unroll
        for (int o = 16; o > 0; o >>= 1) {
            lp += __shfl_down_sync(0xffffffff, lp, o);
            lc += __shfl_down_sync(0xffffffff, lc, o);
        }
        if (t == 0) {
            out[0] = lp * 0.5f;          // / B
            out[1] = lc * (1.0f / 6.0f); // / (B*3)
            g_ctr = 0;                   // reset for next graph replay
        }
    }
}

extern "C" void kernel_launch(void* const* d_in, const int* in_sizes, int n_in,
                              void* d_out, int out_size) {
    const float* Xv = (const float*)d_in[0];
    const float* Tv = (const float*)d_in[1];
    const float* w  = (const float*)d_in[2];
    float* out = (float*)d_out;

    chamfer_kernel<<<NBLK, TPB>>>(Xv, Tv, w, out);
}

// round 5
// speedup vs baseline: 1.1740x; 1.0391x over previous
#include <cuda_runtime.h>
#include <math.h>

typedef unsigned long long u64;

// Problem shape (fixed): B=2, S=8, N=2048, D=3
#define NPTS   2048
#define TPB    128
#define QPB    64                   // queries per block (2 threads per query)
#define CHUNKS (NPTS / QPB)         // 32
#define NSETS  16                   // B*S
#define NBLK   (NSETS * 2 * CHUNKS) // 1024 blocks

#define NJP    (NPTS / 2)           // 1024 lane-pairs total
#define HJP    (NJP / 2)            // 512 lane-pairs per half
#define HPAD   (HJP + 1)            // +1 entry -> halves offset by 4 banks

#define IDX_MASK 0x7FFu             // 11 bits for j in [0, 2048)
#define KEY_MASK 0xFFFFF800u

__device__ float g_loss_part[NBLK];
__device__ float g_cent_part[NBLK][3];
__device__ unsigned int g_ctr = 0;   // self-resetting completion counter

__device__ __forceinline__ float smooth_l1(float a, float b) {
    float d = fabsf(a - b);
    return (d < 1.0f) ? (0.5f * d * d) : (d - 0.5f);
}

// Blackwell packed f32x2 FMA (only reachable via PTX)
#define FMA2(d, a, b, c) \
    asm("fma.rn.f32x2 %0, %1, %2, %3;" : "=l"(d) : "l"(a), "l"(b), "l"(c))
#define PACK2(d, lo, hi) \
    asm("mov.b64 %0, {%1, %2};" : "=l"(d) : "f"(lo), "f"(hi))
#define UNPACK2(lo, hi, s) \
    asm("mov.b64 {%0, %1}, %2;" : "=f"(lo), "=f"(hi) : "l"(s))

__global__ __launch_bounds__(TPB, 6)
void chamfer_kernel(const float* __restrict__ Xv, const float* __restrict__ Tv,
                    const float* __restrict__ w, float* __restrict__ out)
{
    const int tid   = threadIdx.x;
    const int blk   = blockIdx.x;
    const int set   = blk / (2 * CHUNKS);
    const int rem   = blk % (2 * CHUNKS);
    const int dir   = rem / CHUNKS;      // 0: queries=X_v, db=target ; 1: swapped
    const int chunk = rem % CHUNKS;

    const float* __restrict__ qg = (dir == 0 ? Xv : Tv) + set * NPTS * 3;
    const float* __restrict__ dg = (dir == 0 ? Tv : Xv) + set * NPTS * 3;

    // Database tile split in halves, interleaved for f32x2 over consecutive-j pairs.
    // shA[h][loc] = { (-2x_j, -2x_{j+1}) , (-2y_j, -2y_{j+1}) }   j = 2*(h*HJP+loc)
    // shB[h][loc] = { (-2z_j, -2z_{j+1}) , ( t2_j,  t2_{j+1}) }
    __shared__ ulonglong2 shA[2][HPAD];    // ~16.4 KB
    __shared__ ulonglong2 shB[2][HPAD];    // ~16.4 KB
    __shared__ float4 red4[TPB];           // 2 KB
    __shared__ unsigned int is_last;

    for (int i = tid; i < NPTS; i += TPB) {
        float x = dg[i * 3 + 0];
        float y = dg[i * 3 + 1];
        float z = dg[i * 3 + 2];
        float n = x * x;
        n = fmaf(y, y, n);
        n = fmaf(z, z, n);
        int jp = i >> 1, l = i & 1;
        int h = jp >> 9, loc = jp & (HJP - 1);
        float* fA = (float*)&shA[h][loc];
        float* fB = (float*)&shB[h][loc];
        fA[0 + l] = -2.0f * x;
        fA[2 + l] = -2.0f * y;
        fB[0 + l] = -2.0f * z;
        fB[2 + l] = n;
    }
    __syncthreads();

    // Query for this thread: q = tid>>1, DB half = tid&1.
    const int q    = tid >> 1;
    const int half = tid & 1;
    const int qi   = chunk * QPB + q;
    const float qx = qg[qi * 3 + 0];
    const float qy = qg[qi * 3 + 1];
    const float qz = qg[qi * 3 + 2];
    u64 qx2, qy2, qz2;
    PACK2(qx2, qx, qx);
    PACK2(qy2, qy, qy);
    PACK2(qz2, qz, qz);

    // Argmin via index-in-mantissa keys over this half's 512 lane-pairs.
    float m0 = 3.0e38f, m1 = 3.0e38f;
    const unsigned jbase = (unsigned)(half * NPTS / 2);   // 0 or 1024
    const ulonglong2* __restrict__ pA = shA[half];
    const ulonglong2* __restrict__ pB = shB[half];

#pragma unroll 8
    for (int loc = 0; loc < HJP; loc++) {
        ulonglong2 va = pA[loc];   // {mx2, my2}
        ulonglong2 vb = pB[loc];   // {mz2, t2x2}
        unsigned j0 = jbase + 2u * (unsigned)loc;
        u64 acc = vb.y;            // key: t2 - 2*q.t (p2 dropped)
        FMA2(acc, qx2, va.x, acc);
        FMA2(acc, qy2, va.y, acc);
        FMA2(acc, qz2, vb.x, acc);
        float d0, d1;
        UNPACK2(d0, d1, acc);
        unsigned k0 = (__float_as_uint(d0) & KEY_MASK) | j0;
        unsigned k1 = (__float_as_uint(d1) & KEY_MASK) | (j0 + 1u);
        m0 = fminf(m0, __uint_as_float(k0));
        m1 = fminf(m1, __uint_as_float(k1));
    }

    // Merge even/odd chains, then merge the two halves across the lane pair.
    float mk = fminf(m0, m1);
    mk = fminf(mk, __shfl_xor_sync(0xffffffffu, mk, 1));

    // Lane half==0 recovers NN and computes partials; half==1 contributes 0.
    float sl = 0.0f, cx = 0.0f, cy = 0.0f, cz = 0.0f;
    if (half == 0) {
        int j  = (int)(__float_as_uint(mk) & IDX_MASK);
        int jp = j >> 1, l = j & 1;
        int h  = jp >> 9, loc = jp & (HJP - 1);
        const float* fA = (const float*)&shA[h][loc];
        const float* fB = (const float*)&shB[h][loc];
        float nx = -0.5f * fA[0 + l];
        float ny = -0.5f * fA[2 + l];
        float nz = -0.5f * fB[0 + l];
        sl  = smooth_l1(qx, nx);
        sl += smooth_l1(qy, ny);
        sl += smooth_l1(qz, nz);
        cx = qx; cy = qy; cz = qz;
    }

    // Deterministic block reduction (fixed tree order).
    red4[tid] = make_float4(sl, cx, cy, cz);
    __syncthreads();
    for (int s = TPB / 2; s > 0; s >>= 1) {
        if (tid < s) {
            float4 a = red4[tid];
            float4 b = red4[tid + s];
            red4[tid] = make_float4(a.x + b.x, a.y + b.y, a.z + b.z, a.w + b.w);
        }
        __syncthreads();
    }
    if (tid == 0) {
        float4 r = red4[0];
        g_loss_part[blk]    = r.x;
        g_cent_part[blk][0] = r.y;
        g_cent_part[blk][1] = r.z;
        g_cent_part[blk][2] = r.w;
        __threadfence();
        unsigned int v = atomicAdd(&g_ctr, 1u);
        is_last = (v == NBLK - 1) ? 1u : 0u;
    }
    __syncthreads();

    // Last block finalizes (deterministic; counter self-resets for graph replay).
    if (is_last && tid < 32) {
        __threadfence();
        const int t = tid;
        float lp = 0.0f, lc = 0.0f;
        if (t < NSETS) {
            float s = 0.0f;
            for (int d = 0; d < 2; d++)
                for (int c = 0; c < CHUNKS; c++)
                    s += g_loss_part[(t * 2 + d) * CHUNKS + c];
            lp = s * (1.0f / (float)(NPTS * 3)) * w[t];

            float pc0 = 0, pc1 = 0, pc2 = 0, tc0 = 0, tc1 = 0, tc2 = 0;
            for (int c = 0; c < CHUNKS; c++) {
                int b0 = (t * 2 + 0) * CHUNKS + c;   // dir 0 queries = X_v
                int b1 = (t * 2 + 1) * CHUNKS + c;   // dir 1 queries = target
                pc0 += g_cent_part[b0][0]; pc1 += g_cent_part[b0][1]; pc2 += g_cent_part[b0][2];
                tc0 += g_cent_part[b1][0]; tc1 += g_cent_part[b1][1]; tc2 += g_cent_part[b1][2];
            }
            const float inv_n = 1.0f / (float)NPTS;
            lc += smooth_l1(pc0 * inv_n, tc0 * inv_n);
            lc += smooth_l1(pc1 * inv_n, tc1 * inv_n);
            lc += smooth_l1(pc2 * inv_n, tc2 * inv_n);
        }
#pragma unroll
        for (int o = 16; o > 0; o >>= 1) {
            lp += __shfl_down_sync(0xffffffff, lp, o);
            lc += __shfl_down_sync(0xffffffff, lc, o);
        }
        if (t == 0) {
            out[0] = lp * 0.5f;          // / B
            out[1] = lc * (1.0f / 6.0f); // / (B*3)
            g_ctr = 0;                   // reset for next graph replay
        }
    }
}

extern "C" void kernel_launch(void* const* d_in, const int* in_sizes, int n_in,
                              void* d_out, int out_size) {
    const float* Xv = (const float*)d_in[0];
    const float* Tv = (const float*)d_in[1];
    const float* w  = (const float*)d_in[2];
    float* out = (float*)d_out;

    chamfer_kernel<<<NBLK, TPB>>>(Xv, Tv, w, out);
}

// round 6
// speedup vs baseline: 1.1806x; 1.0056x over previous
#include <cuda_runtime.h>
#include <math.h>

typedef unsigned long long u64;

// Problem shape (fixed): B=2, S=8, N=2048, D=3
#define NPTS   2048
#define TPB    256
#define QPT    2                    // queries per thread
#define SPLIT  4                    // DB split across lanes of a group
#define QPB    128                  // queries per block = (TPB/SPLIT)*QPT
#define CHUNKS (NPTS / QPB)         // 16
#define NSETS  16                   // B*S
#define NBLK   (NSETS * 2 * CHUNKS) // 512 blocks -> single wave

#define NJP    (NPTS / 2)           // 1024 lane-pairs total
#define QJP    (NJP / SPLIT)        // 256 lane-pairs per quarter
#define QPAD   (QJP + 1)            // quarters offset by 4 banks

#define IDX_MASK 0x7FFu             // 11 bits for j in [0, 2048)
#define KEY_MASK 0xFFFFF800u

__device__ float g_loss_part[NBLK];
__device__ float g_cent_part[NBLK][3];
__device__ unsigned int g_ctr = 0;   // self-resetting completion counter

__device__ __forceinline__ float smooth_l1(float a, float b) {
    float d = fabsf(a - b);
    return (d < 1.0f) ? (0.5f * d * d) : (d - 0.5f);
}

// Blackwell packed f32x2 FMA (only reachable via PTX)
#define FMA2(d, a, b, c) \
    asm("fma.rn.f32x2 %0, %1, %2, %3;" : "=l"(d) : "l"(a), "l"(b), "l"(c))
#define PACK2(d, lo, hi) \
    asm("mov.b64 %0, {%1, %2};" : "=l"(d) : "f"(lo), "f"(hi))
#define UNPACK2(lo, hi, s) \
    asm("mov.b64 {%0, %1}, %2;" : "=f"(lo), "=f"(hi) : "l"(s))

__global__ __launch_bounds__(TPB, 4)
void chamfer_kernel(const float* __restrict__ Xv, const float* __restrict__ Tv,
                    const float* __restrict__ w, float* __restrict__ out)
{
    const int tid   = threadIdx.x;
    const int blk   = blockIdx.x;
    const int set   = blk / (2 * CHUNKS);
    const int rem   = blk % (2 * CHUNKS);
    const int dir   = rem / CHUNKS;      // 0: queries=X_v, db=target ; 1: swapped
    const int chunk = rem % CHUNKS;

    const float* __restrict__ qg = (dir == 0 ? Xv : Tv) + set * NPTS * 3;
    const float* __restrict__ dg = (dir == 0 ? Tv : Xv) + set * NPTS * 3;

    // DB tile in quarters, interleaved for f32x2 over consecutive-j pairs.
    // shA[qt][loc] = { (-2x_j, -2x_{j+1}) , (-2y_j, -2y_{j+1}) },  jp = qt*QJP + loc
    // shB[qt][loc] = { (-2z_j, -2z_{j+1}) , ( t2_j,  t2_{j+1}) }
    __shared__ ulonglong2 shA[SPLIT][QPAD];   // ~16.1 KB
    __shared__ ulonglong2 shB[SPLIT][QPAD];   // ~16.1 KB
    __shared__ float4 red4[TPB];              // 4 KB
    __shared__ unsigned int is_last;

    for (int i = tid; i < NPTS; i += TPB) {
        float x = dg[i * 3 + 0];
        float y = dg[i * 3 + 1];
        float z = dg[i * 3 + 2];
        float n = x * x;
        n = fmaf(y, y, n);
        n = fmaf(z, z, n);
        int jp = i >> 1, l = i & 1;
        int qt = jp / QJP, loc = jp % QJP;
        float* fA = (float*)&shA[qt][loc];
        float* fB = (float*)&shB[qt][loc];
        fA[0 + l] = -2.0f * x;
        fA[2 + l] = -2.0f * y;
        fB[0 + l] = -2.0f * z;
        fB[2 + l] = n;
    }
    __syncthreads();

    // Group g owns 2 queries; lane's quarter = tid&3.
    const int g    = tid >> 2;           // 0..63
    const int qt   = tid & 3;
    const int qi0  = chunk * QPB + g;            // query 0
    const int qi1  = chunk * QPB + 64 + g;       // query 1
    const float qx0 = qg[qi0 * 3 + 0], qy0 = qg[qi0 * 3 + 1], qz0 = qg[qi0 * 3 + 2];
    const float qx1 = qg[qi1 * 3 + 0], qy1 = qg[qi1 * 3 + 1], qz1 = qg[qi1 * 3 + 2];
    u64 qx20, qy20, qz20, qx21, qy21, qz21;
    PACK2(qx20, qx0, qx0); PACK2(qy20, qy0, qy0); PACK2(qz20, qz0, qz0);
    PACK2(qx21, qx1, qx1); PACK2(qy21, qy1, qy1); PACK2(qz21, qz1, qz1);

    // 4 independent FMNMX chains (2 per query: even/odd candidate lane).
    float m00 = 3.0e38f, m01 = 3.0e38f, m10 = 3.0e38f, m11 = 3.0e38f;
    const unsigned jbase = (unsigned)(qt * 2 * QJP);
    const ulonglong2* __restrict__ pA = shA[qt];
    const ulonglong2* __restrict__ pB = shB[qt];

    // Argmin key: t2_j - 2*q.t_j  (p2 constant per query -> dropped).
#pragma unroll 4
    for (int loc = 0; loc < QJP; loc++) {
        ulonglong2 va = pA[loc];   // {mx2, my2}
        ulonglong2 vb = pB[loc];   // {mz2, t2x2}
        unsigned j0 = jbase + 2u * (unsigned)loc;

        u64 a0 = vb.y;
        FMA2(a0, qx20, va.x, a0);
        FMA2(a0, qy20, va.y, a0);
        FMA2(a0, qz20, vb.x, a0);
        u64 a1 = vb.y;
        FMA2(a1, qx21, va.x, a1);
        FMA2(a1, qy21, va.y, a1);
        FMA2(a1, qz21, vb.x, a1);

        float d00, d01, d10, d11;
        UNPACK2(d00, d01, a0);
        UNPACK2(d10, d11, a1);
        unsigned k00 = (__float_as_uint(d00) & KEY_MASK) | j0;
        unsigned k01 = (__float_as_uint(d01) & KEY_MASK) | (j0 + 1u);
        unsigned k10 = (__float_as_uint(d10) & KEY_MASK) | j0;
        unsigned k11 = (__float_as_uint(d11) & KEY_MASK) | (j0 + 1u);
        m00 = fminf(m00, __uint_as_float(k00));
        m01 = fminf(m01, __uint_as_float(k01));
        m10 = fminf(m10, __uint_as_float(k10));
        m11 = fminf(m11, __uint_as_float(k11));
    }

    // Merge even/odd, then across the 4-lane group (2 shfl_xor).
    float mk0 = fminf(m00, m01);
    float mk1 = fminf(m10, m11);
    mk0 = fminf(mk0, __shfl_xor_sync(0xffffffffu, mk0, 1));
    mk0 = fminf(mk0, __shfl_xor_sync(0xffffffffu, mk0, 2));
    mk1 = fminf(mk1, __shfl_xor_sync(0xffffffffu, mk1, 1));
    mk1 = fminf(mk1, __shfl_xor_sync(0xffffffffu, mk1, 2));

    // Lane qt==0 recovers NNs and computes partials.
    float sl = 0.0f, cx = 0.0f, cy = 0.0f, cz = 0.0f;
    if (qt == 0) {
        {
            int j  = (int)(__float_as_uint(mk0) & IDX_MASK);
            int jp = j >> 1, l = j & 1;
            int qq = jp / QJP, loc = jp % QJP;
            const float* fA = (const float*)&shA[qq][loc];
            const float* fB = (const float*)&shB[qq][loc];
            sl += smooth_l1(qx0, -0.5f * fA[0 + l]);
            sl += smooth_l1(qy0, -0.5f * fA[2 + l]);
            sl += smooth_l1(qz0, -0.5f * fB[0 + l]);
        }
        {
            int j  = (int)(__float_as_uint(mk1) & IDX_MASK);
            int jp = j >> 1, l = j & 1;
            int qq = jp / QJP, loc = jp % QJP;
            const float* fA = (const float*)&shA[qq][loc];
            const float* fB = (const float*)&shB[qq][loc];
            sl += smooth_l1(qx1, -0.5f * fA[0 + l]);
            sl += smooth_l1(qy1, -0.5f * fA[2 + l]);
            sl += smooth_l1(qz1, -0.5f * fB[0 + l]);
        }
        cx = qx0 + qx1; cy = qy0 + qy1; cz = qz0 + qz1;
    }

    // Deterministic block reduction (fixed tree order).
    red4[tid] = make_float4(sl, cx, cy, cz);
    __syncthreads();
    for (int s = TPB / 2; s > 0; s >>= 1) {
        if (tid < s) {
            float4 a = red4[tid];
            float4 b = red4[tid + s];
            red4[tid] = make_float4(a.x + b.x, a.y + b.y, a.z + b.z, a.w + b.w);
        }
        __syncthreads();
    }
    if (tid == 0) {
        float4 r = red4[0];
        g_loss_part[blk]    = r.x;
        g_cent_part[blk][0] = r.y;
        g_cent_part[blk][1] = r.z;
        g_cent_part[blk][2] = r.w;
        __threadfence();
        unsigned int v = atomicAdd(&g_ctr, 1u);
        is_last = (v == NBLK - 1) ? 1u : 0u;
    }
    __syncthreads();

    // Last block finalizes (deterministic; counter self-resets for graph replay).
    if (is_last && tid < 32) {
        __threadfence();
        const int t = tid;
        float lp = 0.0f, lc = 0.0f;
        if (t < NSETS) {
            float s = 0.0f;
            for (int d = 0; d < 2; d++)
                for (int c = 0; c < CHUNKS; c++)
                    s += g_loss_part[(t * 2 + d) * CHUNKS + c];
            lp = s * (1.0f / (float)(NPTS * 3)) * w[t];

            float pc0 = 0, pc1 = 0, pc2 = 0, tc0 = 0, tc1 = 0, tc2 = 0;
            for (int c = 0; c < CHUNKS; c++) {
                int b0 = (t * 2 + 0) * CHUNKS + c;   // dir 0 queries = X_v
                int b1 = (t * 2 + 1) * CHUNKS + c;   // dir 1 queries = target
                pc0 += g_cent_part[b0][0]; pc1 += g_cent_part[b0][1]; pc2 += g_cent_part[b0][2];
                tc0 += g_cent_part[b1][0]; tc1 += g_cent_part[b1][1]; tc2 += g_cent_part[b1][2];
            }
            const float inv_n = 1.0f / (float)NPTS;
            lc += smooth_l1(pc0 * inv_n, tc0 * inv_n);
            lc += smooth_l1(pc1 * inv_n, tc1 * inv_n);
            lc += smooth_l1(pc2 * inv_n, tc2 * inv_n);
        }
#pragma unroll
        for (int o = 16; o > 0; o >>= 1) {
            lp += __shfl_down_sync(0xffffffff, lp, o);
            lc += __shfl_down_sync(0xffffffff, lc, o);
        }
        if (t == 0) {
            out[0] = lp * 0.5f;          // / B
            out[1] = lc * (1.0f / 6.0f); // / (B*3)
            g_ctr = 0;                   // reset for next graph replay
        }
    }
}

extern "C" void kernel_launch(void* const* d_in, const int* in_sizes, int n_in,
                              void* d_out, int out_size) {
    const float* Xv = (const float*)d_in[0];
    const float* Tv = (const float*)d_in[1];
    const float* w  = (const float*)d_in[2];
    float* out = (float*)d_out;

    chamfer_kernel<<<NBLK, TPB>>>(Xv, Tv, w, out);
}